// round 8
// baseline (speedup 1.0000x reference)
#include <cuda_runtime.h>
#include <cuda_bf16.h>

// Problem constants
#define T_STEPS 256
#define B_SZ    128
#define F_SZ    2500
#define H_SZ    128
#define O_SZ    2
#define K_SPLIT_AT 1248            // split-K boundary (multiple of 32)

typedef unsigned long long u64;

// Scratch (allocation-free rule: __device__ globals)
__device__ float  g_part[2 * T_STEPS * B_SZ * H_SZ]; // split-K partials [s][t][b][h]
__device__ float  g_spk1[T_STEPS * B_SZ * H_SZ];     // [t][b][h]
__device__ double g_cur2[T_STEPS * B_SZ * O_SZ];     // [t][b][o]

// ---- packed f32x2 helpers (sm_103a) ---------------------------------------
__device__ __forceinline__ u64 ffma2(u64 a, u64 b, u64 c) {
    u64 d; asm("fma.rn.f32x2 %0,%1,%2,%3;" : "=l"(d) : "l"(a), "l"(b), "l"(c)); return d;
}
__device__ __forceinline__ u64 fadd2(u64 a, u64 b) {
    u64 d; asm("add.rn.f32x2 %0,%1,%2;" : "=l"(d) : "l"(a), "l"(b)); return d;
}
__device__ __forceinline__ u64 fsub2(u64 a, u64 b) {
    u64 d; asm("sub.rn.f32x2 %0,%1,%2;" : "=l"(d) : "l"(a), "l"(b)); return d;
}
__device__ __forceinline__ void upk2(u64 p, float& lo, float& hi) {
    asm("mov.b64 {%0,%1},%2;" : "=f"(lo), "=f"(hi) : "l"(p));
}

// ---------------------------------------------------------------------------
// Kernel 1: split-K GEMM partials:
//   part[ks][t,b,h] = sum_{f in half ks} x[b,t,f] * W1[h,f]
// grid = (bm:2, ks:2, t:256). Tile BM=64 x BN=128, BK=32, 4x8/thread, 256 thr.
// Packed FFMA2 mainloop (4 LDS.128 + 16 FFMA2 per k, zero MOVs):
//   - X tile stored pre-duplicated as float2(v,v) -> aP via direct LDS.128
//   - W pairs read as ulonglong2 (adjacent floats are already packed f32x2)
// Precision: fresh chunk accumulator per BK=32, Kahan-merged per half; halves
// combined in fp64 in lif1.  launch_bounds(256,1): no reg cap -> no spills.
// Software pipeline: prefetch next chunk's LDG into regs during compute.
// ---------------------------------------------------------------------------
__global__ void __launch_bounds__(256, 1) gemm1_kernel(
    const float* __restrict__ x,   // [B, T, F]
    const float* __restrict__ W1)  // [H, F]
{
    const int bm  = blockIdx.x;            // 0..1 (b tile)
    const int ks  = blockIdx.y;            // 0..1 (K half)
    const int t   = blockIdx.z;            // 0..255
    const int tid = threadIdx.x;

    const int kbase   = ks ? K_SPLIT_AT : 0;
    const int nchunks = ks ? 40 : 39;      // ks1 covers [1248,2500), last partial

    __shared__ float2 Xs2[32][66];         // [k][b] duplicated pairs, 16B-aligned rows
    __shared__ float  Ws [32][132];        // [k][h], +4 pad

    u64 accP[4][4], compP[4][4], caccP[4][4];
    #pragma unroll
    for (int i = 0; i < 4; i++)
        #pragma unroll
        for (int j = 0; j < 4; j++) { accP[i][j] = 0ull; compP[i][j] = 0ull; }

    const int tr = tid >> 4;   // 0..15 -> b rows tr*4..+3
    const int tc = tid & 15;   // 0..15 -> h cols tc*8..+7

    // Loader geometry (per chunk): X 2 float4/thread, W 4 float4/thread
    const int xr  = tid >> 3;              // base row helper
    const int xkv = (tid & 7) << 2;        // 0,4,...,28

    float4 px[2], pw[4];

    // ---- chunk loader into registers ----
    auto load_chunk = [&](int c) {
        const int k0 = kbase + c * 32;
        #pragma unroll
        for (int i = 0; i < 2; i++) {
            const int r = xr + 32 * i;     // 0..63
            const int f = k0 + xkv;
            px[i] = make_float4(0.f, 0.f, 0.f, 0.f);
            if (f < F_SZ)
                px[i] = __ldcs(reinterpret_cast<const float4*>(
                           &x[((bm * 64 + r) * T_STEPS + t) * F_SZ + f]));
        }
        #pragma unroll
        for (int i = 0; i < 4; i++) {
            const int r = xr + 32 * i;     // 0..127
            const int f = k0 + xkv;
            pw[i] = make_float4(0.f, 0.f, 0.f, 0.f);
            if (f < F_SZ)
                pw[i] = *reinterpret_cast<const float4*>(&W1[r * F_SZ + f]);
        }
    };
    // ---- registers -> smem ----
    auto store_chunk = [&]() {
        #pragma unroll
        for (int i = 0; i < 2; i++) {
            const int r = xr + 32 * i;
            Xs2[xkv + 0][r] = make_float2(px[i].x, px[i].x);
            Xs2[xkv + 1][r] = make_float2(px[i].y, px[i].y);
            Xs2[xkv + 2][r] = make_float2(px[i].z, px[i].z);
            Xs2[xkv + 3][r] = make_float2(px[i].w, px[i].w);
        }
        #pragma unroll
        for (int i = 0; i < 4; i++) {
            const int r = xr + 32 * i;
            Ws[xkv + 0][r] = pw[i].x; Ws[xkv + 1][r] = pw[i].y;
            Ws[xkv + 2][r] = pw[i].z; Ws[xkv + 3][r] = pw[i].w;
        }
    };

    load_chunk(0);
    store_chunk();
    __syncthreads();

    for (int c = 0; c < nchunks; c++) {
        const bool more = (c + 1 < nchunks);
        if (more) load_chunk(c + 1);       // LDG in flight during compute

        #pragma unroll
        for (int i = 0; i < 4; i++)
            #pragma unroll
            for (int j = 0; j < 4; j++) caccP[i][j] = 0ull;

        #pragma unroll 8
        for (int k = 0; k < 32; k++) {
            // aP: duplicated X pairs, 32B contiguous -> 2x LDS.128
            const ulonglong2* ap =
                reinterpret_cast<const ulonglong2*>(&Xs2[k][tr * 4]);
            ulonglong2 a01 = ap[0], a23 = ap[1];
            // bP: adjacent W floats = packed f32x2 -> 2x LDS.128
            const ulonglong2* bp =
                reinterpret_cast<const ulonglong2*>(&Ws[k][tc * 8]);
            ulonglong2 b01 = bp[0], b23 = bp[1];
            u64 aP[4] = { a01.x, a01.y, a23.x, a23.y };
            u64 bP[4] = { b01.x, b01.y, b23.x, b23.y };
            #pragma unroll
            for (int i = 0; i < 4; i++)
                #pragma unroll
                for (int j = 0; j < 4; j++)
                    caccP[i][j] = ffma2(aP[i], bP[j], caccP[i][j]);
        }

        // Kahan merge (packed) of chunk sum into running accumulator
        #pragma unroll
        for (int i = 0; i < 4; i++)
            #pragma unroll
            for (int j = 0; j < 4; j++) {
                u64 y   = fsub2(caccP[i][j], compP[i][j]);
                u64 tmp = fadd2(accP[i][j], y);
                compP[i][j] = fsub2(fsub2(tmp, accP[i][j]), y);
                accP[i][j]  = tmp;
            }

        if (more) {
            __syncthreads();   // everyone done reading smem
            store_chunk();
            __syncthreads();   // stores visible
        }
    }

    // Store fp32 partial (acc + comp); bias added later in fp64 in lif1.
    float* base = g_part + (size_t)ks * (T_STEPS * B_SZ * H_SZ);
    #pragma unroll
    for (int i = 0; i < 4; i++) {
        const int brow = bm * 64 + tr * 4 + i;
        float* dst = &base[(t * B_SZ + brow) * H_SZ + tc * 8];
        float r[8];
        #pragma unroll
        for (int j = 0; j < 4; j++) {
            u64 v = fadd2(accP[i][j], compP[i][j]);
            upk2(v, r[2 * j], r[2 * j + 1]);
        }
        *reinterpret_cast<float4*>(dst)     = *reinterpret_cast<float4*>(r);
        *reinterpret_cast<float4*>(dst + 4) = *reinterpret_cast<float4*>(r + 4);
    }
}

// ---------------------------------------------------------------------------
// Kernel 2: fused split-K merge + LIF layer 1 (fp64).
// One thread per (b,h) = 16384 threads.
// cur1 = (double)p0 + (double)p1 + (double)b1[h];  mem = beta*mem+cur1 - rst.
// ---------------------------------------------------------------------------
__global__ void lif1_kernel(const float* __restrict__ b1)
{
    const int g = blockIdx.x * blockDim.x + threadIdx.x;  // b*H + h
    const double bias = (double)b1[g & (H_SZ - 1)];
    const double beta = (double)0.9f;  // match reference's fp32 constant
    const float* p0 = g_part;
    const float* p1 = g_part + T_STEPS * B_SZ * H_SZ;

    double mem = 0.0;
    for (int t0 = 0; t0 < T_STEPS; t0 += 8) {
        double c[8];
        #pragma unroll
        for (int i = 0; i < 8; i++) {
            const int idx = (t0 + i) * (B_SZ * H_SZ) + g;
            c[i] = (double)p0[idx] + (double)p1[idx] + bias;
        }
        #pragma unroll
        for (int i = 0; i < 8; i++) {
            const double rst = (mem > 1.0) ? 1.0 : 0.0;
            mem = fma(beta, mem, c[i]) - rst;   // (beta*mem + c) - rst
            g_spk1[(t0 + i) * (B_SZ * H_SZ) + g] = (mem > 1.0) ? 1.0f : 0.0f;
        }
    }
}

// ---------------------------------------------------------------------------
// Kernel 3: cur2[t,b,o] = sum_h spk1[t,b,h] * W2[o,h] + b2[o]  (fp64 exact:
// spk1 in {0,1} so products are exact fp32, summed in double).
// One warp per (t,b): 32768 warps.
// ---------------------------------------------------------------------------
__global__ void cur2_kernel(const float* __restrict__ W2, const float* __restrict__ b2)
{
    const int gw   = (blockIdx.x * blockDim.x + threadIdx.x) >> 5;  // t*B + b
    const int lane = threadIdx.x & 31;
    const float* row = g_spk1 + (size_t)gw * H_SZ;

    double s0 = 0.0, s1 = 0.0;
    #pragma unroll
    for (int j = 0; j < 4; j++) {
        const int h = lane + j * 32;
        const float v = row[h];
        s0 += (double)(v * W2[h]);
        s1 += (double)(v * W2[H_SZ + h]);
    }
    #pragma unroll
    for (int off = 16; off > 0; off >>= 1) {
        s0 += __shfl_xor_sync(0xffffffffu, s0, off);
        s1 += __shfl_xor_sync(0xffffffffu, s1, off);
    }
    if (lane == 0) {
        g_cur2[gw * 2 + 0] = s0 + (double)b2[0];
        g_cur2[gw * 2 + 1] = s1 + (double)b2[1];
    }
}

// ---------------------------------------------------------------------------
// Kernel 4: LIF layer 2 + outputs, in fp32 (cur2 already exact-rounded fp64;
// fp32 chain is ~5x shorter latency than the fp64 DFMA chain: 58us -> ~6us).
// One thread per (b,o) chain = 256 threads over 8 blocks.
// out = [spk_rec (T,B,O) | mem_rec (T,B,O)] flattened, fp32.
// ---------------------------------------------------------------------------
__global__ void lif2_kernel(float* __restrict__ out)
{
    const int g = blockIdx.x * blockDim.x + threadIdx.x;  // b*O + o, 0..255
    float* out_spk = out;
    float* out_mem = out + T_STEPS * B_SZ * O_SZ;

    float mem = 0.f;
    for (int t0 = 0; t0 < T_STEPS; t0 += 8) {
        float c[8];
        #pragma unroll
        for (int i = 0; i < 8; i++)
            c[i] = (float)g_cur2[(t0 + i) * (B_SZ * O_SZ) + g];
        #pragma unroll
        for (int i = 0; i < 8; i++) {
            const float rst = (mem > 1.0f) ? 1.0f : 0.0f;
            mem = fmaf(0.9f, mem, c[i]) - rst;
            out_spk[(t0 + i) * (B_SZ * O_SZ) + g] = (mem > 1.0f) ? 1.0f : 0.0f;
            out_mem[(t0 + i) * (B_SZ * O_SZ) + g] = mem;
        }
    }
}

// ---------------------------------------------------------------------------
extern "C" void kernel_launch(void* const* d_in, const int* in_sizes, int n_in,
                              void* d_out, int out_size)
{
    const float* x  = (const float*)d_in[0];  // [B, T, F]
    const float* W1 = (const float*)d_in[1];  // [H, F]
    const float* b1 = (const float*)d_in[2];  // [H]
    const float* W2 = (const float*)d_in[3];  // [O, H]
    const float* b2 = (const float*)d_in[4];  // [O]
    float* out = (float*)d_out;

    dim3 g1(2, 2, T_STEPS);                                    // bm, ks, t
    gemm1_kernel<<<g1, 256>>>(x, W1);                          // 1024 CTAs
    lif1_kernel<<<(B_SZ * H_SZ) / 256, 256>>>(b1);             // 64 CTAs
    cur2_kernel<<<(T_STEPS * B_SZ * 32) / 256, 256>>>(W2, b2); // 4096 CTAs
    lif2_kernel<<<8, 32>>>(out);                               // tiny serial tail
}

// round 9
// speedup vs baseline: 1.6758x; 1.6758x over previous
#include <cuda_runtime.h>
#include <cuda_bf16.h>

// Problem constants
#define T_STEPS 256
#define B_SZ    128
#define F_SZ    2500
#define H_SZ    128
#define O_SZ    2
#define K_SPLIT_AT 1248            // split-K boundary (multiple of 32)

typedef unsigned long long u64;

// Scratch (allocation-free rule: __device__ globals)
__device__ float  g_part[2 * T_STEPS * B_SZ * H_SZ]; // split-K partials [s][t][b][h]
__device__ float  g_spk1[T_STEPS * B_SZ * H_SZ];     // [t][b][h]

// ---- packed f32x2 helpers (sm_103a) ---------------------------------------
__device__ __forceinline__ u64 ffma2(u64 a, u64 b, u64 c) {
    u64 d; asm("fma.rn.f32x2 %0,%1,%2,%3;" : "=l"(d) : "l"(a), "l"(b), "l"(c)); return d;
}
__device__ __forceinline__ u64 fadd2(u64 a, u64 b) {
    u64 d; asm("add.rn.f32x2 %0,%1,%2;" : "=l"(d) : "l"(a), "l"(b)); return d;
}
__device__ __forceinline__ void upk2(u64 p, float& lo, float& hi) {
    asm("mov.b64 {%0,%1},%2;" : "=f"(lo), "=f"(hi) : "l"(p));
}

// ---------------------------------------------------------------------------
// Kernel 1: split-K GEMM partials:
//   part[ks][t,b,h] = sum_{f in half ks} x[b,t,f] * W1[h,f]
// grid = (bm:2, ks:2, t:256), 256 thr, OCC 2 (the R8 occ-1 regression lesson).
// Tile BM=64 x BN=128, BK=32, 4x8/thread.
// MOV-free packed FFMA2 mainloop (4 LDS.128 + 16 FFMA2 per k):
//   - X tile stored pre-duplicated as float2(v,v) -> aP via direct LDS.128
//   - W pairs read as ulonglong2 (adjacent floats are already packed f32x2)
// Precision: fresh chunk accumulator per BK=32 (plain merge, no Kahan ->
// fits 128-reg cap); per-half error ~8e-8, halves merged in fp64 in lif1.
// ---------------------------------------------------------------------------
__global__ void __launch_bounds__(256, 2) gemm1_kernel(
    const float* __restrict__ x,   // [B, T, F]
    const float* __restrict__ W1)  // [H, F]
{
    const int bm  = blockIdx.x;            // 0..1 (b tile)
    const int ks  = blockIdx.y;            // 0..1 (K half)
    const int t   = blockIdx.z;            // 0..255
    const int tid = threadIdx.x;

    const int kbase   = ks ? K_SPLIT_AT : 0;
    const int nchunks = ks ? 40 : 39;      // ks1 covers [1248,2500), last partial

    __shared__ float2 Xs2[32][66];         // [k][b] duplicated pairs
    __shared__ float  Ws [32][132];        // [k][h], +4 pad

    u64 accP[4][4], caccP[4][4];
    #pragma unroll
    for (int i = 0; i < 4; i++)
        #pragma unroll
        for (int j = 0; j < 4; j++) accP[i][j] = 0ull;

    const int tr = tid >> 4;   // 0..15 -> b rows tr*4..+3
    const int tc = tid & 15;   // 0..15 -> h cols tc*8..+7

    // Loader geometry (per chunk): X 2 float4/thread, W 4 float4/thread
    const int xr  = tid >> 3;              // base row helper
    const int xkv = (tid & 7) << 2;        // 0,4,...,28

    for (int c = 0; c < nchunks; c++) {
        const int k0 = kbase + c * 32;
        // Load X: 64 rows x 32 k, pre-duplicated into float2 pairs.
        #pragma unroll
        for (int i = 0; i < 2; i++) {
            const int r = xr + 32 * i;     // 0..63
            const int f = k0 + xkv;
            float4 v = make_float4(0.f, 0.f, 0.f, 0.f);
            if (f < F_SZ)                  // F_SZ%4==0 -> float4 valid or OOB
                v = __ldcs(reinterpret_cast<const float4*>(
                        &x[((bm * 64 + r) * T_STEPS + t) * F_SZ + f]));
            Xs2[xkv + 0][r] = make_float2(v.x, v.x);
            Xs2[xkv + 1][r] = make_float2(v.y, v.y);
            Xs2[xkv + 2][r] = make_float2(v.z, v.z);
            Xs2[xkv + 3][r] = make_float2(v.w, v.w);
        }
        // Load W: 128 rows x 32 k.
        #pragma unroll
        for (int i = 0; i < 4; i++) {
            const int r = xr + 32 * i;     // 0..127
            const int f = k0 + xkv;
            float4 v = make_float4(0.f, 0.f, 0.f, 0.f);
            if (f < F_SZ)
                v = *reinterpret_cast<const float4*>(&W1[r * F_SZ + f]);
            Ws[xkv + 0][r] = v.x; Ws[xkv + 1][r] = v.y;
            Ws[xkv + 2][r] = v.z; Ws[xkv + 3][r] = v.w;
        }
        __syncthreads();

        #pragma unroll
        for (int i = 0; i < 4; i++)
            #pragma unroll
            for (int j = 0; j < 4; j++) caccP[i][j] = 0ull;

        #pragma unroll 8
        for (int k = 0; k < 32; k++) {
            // aP: duplicated X pairs -> 2x LDS.128 (broadcast within half-warp)
            const ulonglong2* ap =
                reinterpret_cast<const ulonglong2*>(&Xs2[k][tr * 4]);
            ulonglong2 a01 = ap[0], a23 = ap[1];
            // bP: adjacent W floats = packed f32x2 -> 2x LDS.128
            const ulonglong2* bp =
                reinterpret_cast<const ulonglong2*>(&Ws[k][tc * 8]);
            ulonglong2 b01 = bp[0], b23 = bp[1];
            u64 aP[4] = { a01.x, a01.y, a23.x, a23.y };
            u64 bP[4] = { b01.x, b01.y, b23.x, b23.y };
            #pragma unroll
            for (int i = 0; i < 4; i++)
                #pragma unroll
                for (int j = 0; j < 4; j++)
                    caccP[i][j] = ffma2(aP[i], bP[j], caccP[i][j]);
        }

        // Plain packed merge of chunk sum into running accumulator
        #pragma unroll
        for (int i = 0; i < 4; i++)
            #pragma unroll
            for (int j = 0; j < 4; j++)
                accP[i][j] = fadd2(accP[i][j], caccP[i][j]);
        __syncthreads();
    }

    // Store fp32 partial; bias + other half merged in fp64 in lif1.
    float* base = g_part + (size_t)ks * (T_STEPS * B_SZ * H_SZ);
    #pragma unroll
    for (int i = 0; i < 4; i++) {
        const int brow = bm * 64 + tr * 4 + i;
        float* dst = &base[(t * B_SZ + brow) * H_SZ + tc * 8];
        float r[8];
        #pragma unroll
        for (int j = 0; j < 4; j++)
            upk2(accP[i][j], r[2 * j], r[2 * j + 1]);
        *reinterpret_cast<float4*>(dst)     = *reinterpret_cast<float4*>(r);
        *reinterpret_cast<float4*>(dst + 4) = *reinterpret_cast<float4*>(r + 4);
    }
}

// ---------------------------------------------------------------------------
// Kernel 2: fused split-K merge + LIF layer 1 (fp64).
// One thread per (b,h) = 16384 threads.
// cur1 = (double)p0 + (double)p1 + (double)b1[h];  mem = beta*mem+cur1 - rst.
// ---------------------------------------------------------------------------
__global__ void lif1_kernel(const float* __restrict__ b1)
{
    const int g = blockIdx.x * blockDim.x + threadIdx.x;  // b*H + h
    const double bias = (double)b1[g & (H_SZ - 1)];
    const double beta = (double)0.9f;  // match reference's fp32 constant
    const float* p0 = g_part;
    const float* p1 = g_part + T_STEPS * B_SZ * H_SZ;

    double mem = 0.0;
    for (int t0 = 0; t0 < T_STEPS; t0 += 8) {
        double c[8];
        #pragma unroll
        for (int i = 0; i < 8; i++) {
            const int idx = (t0 + i) * (B_SZ * H_SZ) + g;
            c[i] = (double)p0[idx] + (double)p1[idx] + bias;
        }
        #pragma unroll
        for (int i = 0; i < 8; i++) {
            const double rst = (mem > 1.0) ? 1.0 : 0.0;
            mem = fma(beta, mem, c[i]) - rst;
            g_spk1[(t0 + i) * (B_SZ * H_SZ) + g] = (mem > 1.0) ? 1.0f : 0.0f;
        }
    }
}

// ---------------------------------------------------------------------------
// Kernel 3 (fused cur2 + LIF2 + outputs): one block per b (128 blocks).
// Phase 1: 8 warps compute cur2[t] = spk1[t,b,:]·W2 + b2 (fp64-exact dots,
//          spk in {0,1}) for all 256 t into smem.
// Phase 2: 2 threads run the serial fp32 LIF chain from smem and write out.
// Replaces the separate cur2 (15us) + serial lif2 (41us) kernels.
// out = [spk_rec (T,B,O) | mem_rec (T,B,O)] flattened, fp32.
// ---------------------------------------------------------------------------
__global__ void __launch_bounds__(256) out_kernel(
    const float* __restrict__ W2, const float* __restrict__ b2,
    float* __restrict__ out)
{
    const int b    = blockIdx.x;           // 0..127
    const int tid  = threadIdx.x;
    const int w    = tid >> 5;             // warp 0..7
    const int lane = tid & 31;

    __shared__ float cur_s[T_STEPS][O_SZ]; // 2 KB

    // Preload W2 rows into registers (broadcast via const cache)
    float w2a[4], w2b[4];
    #pragma unroll
    for (int j = 0; j < 4; j++) {
        w2a[j] = W2[lane + j * 32];
        w2b[j] = W2[H_SZ + lane + j * 32];
    }

    for (int t = w; t < T_STEPS; t += 8) {
        const float* row = g_spk1 + ((size_t)t * B_SZ + b) * H_SZ;
        double s0 = 0.0, s1 = 0.0;
        #pragma unroll
        for (int j = 0; j < 4; j++) {
            const float v = row[lane + j * 32];
            s0 += (double)(v * w2a[j]);
            s1 += (double)(v * w2b[j]);
        }
        #pragma unroll
        for (int off = 16; off > 0; off >>= 1) {
            s0 += __shfl_xor_sync(0xffffffffu, s0, off);
            s1 += __shfl_xor_sync(0xffffffffu, s1, off);
        }
        if (lane == 0) {
            cur_s[t][0] = (float)(s0 + (double)b2[0]);
            cur_s[t][1] = (float)(s1 + (double)b2[1]);
        }
    }
    __syncthreads();

    if (tid < O_SZ) {
        float* out_spk = out;
        float* out_mem = out + T_STEPS * B_SZ * O_SZ;
        float mem = 0.f;
        for (int t = 0; t < T_STEPS; t++) {
            const float rst = (mem > 1.0f) ? 1.0f : 0.0f;
            mem = fmaf(0.9f, mem, cur_s[t][tid]) - rst;
            const int o = (t * B_SZ + b) * O_SZ + tid;
            out_spk[o] = (mem > 1.0f) ? 1.0f : 0.0f;
            out_mem[o] = mem;
        }
    }
}

// ---------------------------------------------------------------------------
extern "C" void kernel_launch(void* const* d_in, const int* in_sizes, int n_in,
                              void* d_out, int out_size)
{
    const float* x  = (const float*)d_in[0];  // [B, T, F]
    const float* W1 = (const float*)d_in[1];  // [H, F]
    const float* b1 = (const float*)d_in[2];  // [H]
    const float* W2 = (const float*)d_in[3];  // [O, H]
    const float* b2 = (const float*)d_in[4];  // [O]
    float* out = (float*)d_out;

    dim3 g1(2, 2, T_STEPS);                         // bm, ks, t
    gemm1_kernel<<<g1, 256>>>(x, W1);               // 1024 CTAs
    lif1_kernel<<<(B_SZ * H_SZ) / 256, 256>>>(b1);  // 64 CTAs
    out_kernel<<<B_SZ, 256>>>(W2, b2, out);         // 128 CTAs
}

// round 13
// speedup vs baseline: 2.3042x; 1.3750x over previous
#include <cuda_runtime.h>
#include <cuda_bf16.h>

// Problem constants
#define T_STEPS 256
#define B_SZ    128
#define F_SZ    2500
#define H_SZ    128
#define O_SZ    2
#define K_SPLIT_AT 1248            // split-K boundary (multiple of 32)

typedef unsigned long long u64;

// Scratch (allocation-free rule: __device__ globals)
__device__ float  g_part[2 * T_STEPS * B_SZ * H_SZ]; // split-K partials [s][t][b][h]
__device__ float  g_spk1[T_STEPS * B_SZ * H_SZ];     // [t][b][h]

// ---- packed f32x2 helpers (sm_103a) ---------------------------------------
__device__ __forceinline__ u64 ffma2(u64 a, u64 b, u64 c) {
    u64 d; asm("fma.rn.f32x2 %0,%1,%2,%3;" : "=l"(d) : "l"(a), "l"(b), "l"(c)); return d;
}
__device__ __forceinline__ u64 fadd2(u64 a, u64 b) {
    u64 d; asm("add.rn.f32x2 %0,%1,%2;" : "=l"(d) : "l"(a), "l"(b)); return d;
}
__device__ __forceinline__ void upk2(u64 p, float& lo, float& hi) {
    asm("mov.b64 {%0,%1},%2;" : "=f"(lo), "=f"(hi) : "l"(p));
}

// ---------------------------------------------------------------------------
// Kernel 1: split-K GEMM partials:
//   part[ks][t,b,h] = sum_{f in half ks} x[b,t,f] * W1[h,f]
// grid = (bm:2, ks:2, t:256), 256 thr, OCC 2.
// Tile BM=64 x BN=128, BK=32, 4x8/thread.
// MOV-free packed FFMA2 mainloop (4 LDS.128 + 16 FFMA2 per k):
//   - X tile stored pre-duplicated as float2(v,v) -> aP via direct LDS.128
//   - W tile split by 16B-unit PARITY into WsE/WsO so each bp LDS.128 reads
//     16 threads x 16B CONTIGUOUS (2 wavefronts, no 4-way bank conflict;
//     R9 ncu: L1TEX 90% / fma 30% was exactly this conflict).
// Precision: fresh chunk accumulator per BK=32, plain merge (error ~8e-8 per
// half), halves merged in fp64 in lif1.  Bit-identical math to R9 (passed).
// ---------------------------------------------------------------------------
__global__ void __launch_bounds__(256, 2) gemm1_kernel(
    const float* __restrict__ x,   // [B, T, F]
    const float* __restrict__ W1)  // [H, F]
{
    const int bm  = blockIdx.x;            // 0..1 (b tile)
    const int ks  = blockIdx.y;            // 0..1 (K half)
    const int t   = blockIdx.z;            // 0..255
    const int tid = threadIdx.x;

    const int kbase   = ks ? K_SPLIT_AT : 0;
    const int nchunks = ks ? 40 : 39;      // ks1 covers [1248,2500), last partial

    __shared__ float2 Xs2[32][66];         // [k][b] duplicated pairs
    __shared__ float  WsE[32][68];         // [k][h: (h&4)==0], unit-contiguous
    __shared__ float  WsO[32][68];         // [k][h: (h&4)==4]

    u64 accP[4][4], caccP[4][4];
    #pragma unroll
    for (int i = 0; i < 4; i++)
        #pragma unroll
        for (int j = 0; j < 4; j++) accP[i][j] = 0ull;

    const int tr = tid >> 4;   // 0..15 -> b rows tr*4..+3
    const int tc = tid & 15;   // 0..15 -> h cols tc*8..+7

    // Loader geometry (per chunk): X 2 float4/thread, W 4 float4/thread
    const int xr  = tid >> 3;              // base row helper
    const int xkv = (tid & 7) << 2;        // 0,4,...,28

    for (int c = 0; c < nchunks; c++) {
        const int k0 = kbase + c * 32;
        // Load X: 64 rows x 32 k, pre-duplicated into float2 pairs.
        #pragma unroll
        for (int i = 0; i < 2; i++) {
            const int r = xr + 32 * i;     // 0..63
            const int f = k0 + xkv;
            float4 v = make_float4(0.f, 0.f, 0.f, 0.f);
            if (f < F_SZ)                  // F_SZ%4==0 -> float4 valid or OOB
                v = __ldcs(reinterpret_cast<const float4*>(
                        &x[((bm * 64 + r) * T_STEPS + t) * F_SZ + f]));
            Xs2[xkv + 0][r] = make_float2(v.x, v.x);
            Xs2[xkv + 1][r] = make_float2(v.y, v.y);
            Xs2[xkv + 2][r] = make_float2(v.z, v.z);
            Xs2[xkv + 3][r] = make_float2(v.w, v.w);
        }
        // Load W: 128 rows (h) x 32 k, scattered by unit parity.
        #pragma unroll
        for (int i = 0; i < 4; i++) {
            const int r = xr + 32 * i;     // h = 0..127
            const int f = k0 + xkv;
            float4 v = make_float4(0.f, 0.f, 0.f, 0.f);
            if (f < F_SZ)
                v = *reinterpret_cast<const float4*>(&W1[r * F_SZ + f]);
            const int col = ((r >> 3) << 2) + (r & 3);   // unit (h>>3), slot h&3
            float* dstK = (r & 4) ? &WsO[0][0] : &WsE[0][0];
            dstK[(xkv + 0) * 68 + col] = v.x;
            dstK[(xkv + 1) * 68 + col] = v.y;
            dstK[(xkv + 2) * 68 + col] = v.z;
            dstK[(xkv + 3) * 68 + col] = v.w;
        }
        __syncthreads();

        #pragma unroll
        for (int i = 0; i < 4; i++)
            #pragma unroll
            for (int j = 0; j < 4; j++) caccP[i][j] = 0ull;

        #pragma unroll 8
        for (int k = 0; k < 32; k++) {
            // aP: duplicated X pairs -> 2x LDS.128 (half-warp broadcast, 1 wf)
            const ulonglong2* ap =
                reinterpret_cast<const ulonglong2*>(&Xs2[k][tr * 4]);
            ulonglong2 a01 = ap[0], a23 = ap[1];
            // bP: h pairs; WsE holds h=8tc..8tc+3 (pairs 0,1), WsO h=8tc+4..+7
            // (pairs 2,3). 16 threads x contiguous 16B -> 2 wf each, no conflict.
            ulonglong2 b01 = *reinterpret_cast<const ulonglong2*>(&WsE[k][tc * 4]);
            ulonglong2 b23 = *reinterpret_cast<const ulonglong2*>(&WsO[k][tc * 4]);
            u64 aP[4] = { a01.x, a01.y, a23.x, a23.y };
            u64 bP[4] = { b01.x, b01.y, b23.x, b23.y };
            #pragma unroll
            for (int i = 0; i < 4; i++)
                #pragma unroll
                for (int j = 0; j < 4; j++)
                    caccP[i][j] = ffma2(aP[i], bP[j], caccP[i][j]);
        }

        // Plain packed merge of chunk sum into running accumulator
        #pragma unroll
        for (int i = 0; i < 4; i++)
            #pragma unroll
            for (int j = 0; j < 4; j++)
                accP[i][j] = fadd2(accP[i][j], caccP[i][j]);
        __syncthreads();
    }

    // Store fp32 partial; bias + other half merged in fp64 in lif1.
    float* base = g_part + (size_t)ks * (T_STEPS * B_SZ * H_SZ);
    #pragma unroll
    for (int i = 0; i < 4; i++) {
        const int brow = bm * 64 + tr * 4 + i;
        float* dst = &base[(t * B_SZ + brow) * H_SZ + tc * 8];
        float r[8];
        #pragma unroll
        for (int j = 0; j < 4; j++)
            upk2(accP[i][j], r[2 * j], r[2 * j + 1]);
        *reinterpret_cast<float4*>(dst)     = *reinterpret_cast<float4*>(r);
        *reinterpret_cast<float4*>(dst + 4) = *reinterpret_cast<float4*>(r + 4);
    }
}

// ---------------------------------------------------------------------------
// Kernel 2: fused split-K merge + LIF layer 1 (fp64).
// One thread per (b,h) = 16384 threads; 128 CTAs so >64 SMs get work.
// cur1 = (double)p0 + (double)p1 + (double)b1[h];  mem = beta*mem+cur1 - rst.
// ---------------------------------------------------------------------------
__global__ void lif1_kernel(const float* __restrict__ b1)
{
    const int g = blockIdx.x * blockDim.x + threadIdx.x;  // b*H + h
    const double bias = (double)b1[g & (H_SZ - 1)];
    const double beta = (double)0.9f;  // match reference's fp32 constant
    const float* p0 = g_part;
    const float* p1 = g_part + T_STEPS * B_SZ * H_SZ;

    double mem = 0.0;
    for (int t0 = 0; t0 < T_STEPS; t0 += 8) {
        double c[8];
        #pragma unroll
        for (int i = 0; i < 8; i++) {
            const int idx = (t0 + i) * (B_SZ * H_SZ) + g;
            c[i] = (double)p0[idx] + (double)p1[idx] + bias;
        }
        #pragma unroll
        for (int i = 0; i < 8; i++) {
            const double rst = (mem > 1.0) ? 1.0 : 0.0;
            mem = fma(beta, mem, c[i]) - rst;
            g_spk1[(t0 + i) * (B_SZ * H_SZ) + g] = (mem > 1.0) ? 1.0f : 0.0f;
        }
    }
}

// ---------------------------------------------------------------------------
// Kernel 3 (fused cur2 + LIF2 + outputs): one block per b (128 blocks).
// Phase 1: 8 warps compute cur2[t] = spk1[t,b,:]·W2 + b2 (fp64-exact dots,
//          spk in {0,1}) for all 256 t into smem.
// Phase 2: 2 threads run the serial fp32 LIF chain from smem and write out.
// out = [spk_rec (T,B,O) | mem_rec (T,B,O)] flattened, fp32.
// ---------------------------------------------------------------------------
__global__ void __launch_bounds__(256) out_kernel(
    const float* __restrict__ W2, const float* __restrict__ b2,
    float* __restrict__ out)
{
    const int b    = blockIdx.x;           // 0..127
    const int tid  = threadIdx.x;
    const int w    = tid >> 5;             // warp 0..7
    const int lane = tid & 31;

    __shared__ float cur_s[T_STEPS][O_SZ]; // 2 KB

    // Preload W2 rows into registers (broadcast via const cache)
    float w2a[4], w2b[4];
    #pragma unroll
    for (int j = 0; j < 4; j++) {
        w2a[j] = W2[lane + j * 32];
        w2b[j] = W2[H_SZ + lane + j * 32];
    }

    for (int t = w; t < T_STEPS; t += 8) {
        const float* row = g_spk1 + ((size_t)t * B_SZ + b) * H_SZ;
        double s0 = 0.0, s1 = 0.0;
        #pragma unroll
        for (int j = 0; j < 4; j++) {
            const float v = row[lane + j * 32];
            s0 += (double)(v * w2a[j]);
            s1 += (double)(v * w2b[j]);
        }
        #pragma unroll
        for (int off = 16; off > 0; off >>= 1) {
            s0 += __shfl_xor_sync(0xffffffffu, s0, off);
            s1 += __shfl_xor_sync(0xffffffffu, s1, off);
        }
        if (lane == 0) {
            cur_s[t][0] = (float)(s0 + (double)b2[0]);
            cur_s[t][1] = (float)(s1 + (double)b2[1]);
        }
    }
    __syncthreads();

    if (tid < O_SZ) {
        float* out_spk = out;
        float* out_mem = out + T_STEPS * B_SZ * O_SZ;
        float mem = 0.f;
        for (int t = 0; t < T_STEPS; t++) {
            const float rst = (mem > 1.0f) ? 1.0f : 0.0f;
            mem = fmaf(0.9f, mem, cur_s[t][tid]) - rst;
            const int o = (t * B_SZ + b) * O_SZ + tid;
            out_spk[o] = (mem > 1.0f) ? 1.0f : 0.0f;
            out_mem[o] = mem;
        }
    }
}

// ---------------------------------------------------------------------------
extern "C" void kernel_launch(void* const* d_in, const int* in_sizes, int n_in,
                              void* d_out, int out_size)
{
    const float* x  = (const float*)d_in[0];  // [B, T, F]
    const float* W1 = (const float*)d_in[1];  // [H, F]
    const float* b1 = (const float*)d_in[2];  // [H]
    const float* W2 = (const float*)d_in[3];  // [O, H]
    const float* b2 = (const float*)d_in[4];  // [O]
    float* out = (float*)d_out;

    dim3 g1(2, 2, T_STEPS);                          // bm, ks, t
    gemm1_kernel<<<g1, 256>>>(x, W1);                // 1024 CTAs
    lif1_kernel<<<(B_SZ * H_SZ) / 128, 128>>>(b1);   // 128 CTAs
    out_kernel<<<B_SZ, 256>>>(W2, b2, out);          // 128 CTAs
}